// round 4
// baseline (speedup 1.0000x reference)
#include <cuda_runtime.h>
#include <cuda_fp16.h>
#include <cstdint>

typedef unsigned long long ull;

constexpr int T_TOK = 16384;
constexpr int H_DIM = 4096;
constexpr int N_E   = 64;
constexpr int TOPK  = 6;
constexpr int S_SEQ = 4096;

constexpr int BM     = 128;           // tokens per CTA
constexpr int BK     = 64;            // fp32 K per stage
constexpr int NSTAGE = H_DIM / BK;    // 64
constexpr int NT     = 256;
constexpr int NBUF   = 3;

constexpr int ABYTES = BM * BK * 2;        // 16384 per split plane (f16)
constexpr int WBYTES = N_E * BK * 2 * 2;   // 16384 (2 splits)
constexpr int STAGE  = 2 * ABYTES + WBYTES; // 49152
constexpr int DYN    = NBUF * STAGE;        // 147456

// static device scratch
__device__ __half g_W1[N_E * H_DIM];
__device__ __half g_W2[N_E * H_DIM];
__device__ float  g_ssum[4][64];
__device__ float  g_cnt [4][64];

// ---------------------------------------------------------------------------
__device__ __forceinline__ uint32_t smem_u32(const void* p) {
    return (uint32_t)__cvta_generic_to_shared(p);
}
__device__ __forceinline__ void cp16(uint32_t dst, const void* src) {
    asm volatile("cp.async.cg.shared.global [%0], [%1], 16;" :: "r"(dst), "l"(src));
}
__device__ __forceinline__ void ldsm4(uint32_t* r, uint32_t a) {
    asm volatile("ldmatrix.sync.aligned.m8n8.x4.shared.b16 {%0,%1,%2,%3}, [%4];"
                 : "=r"(r[0]), "=r"(r[1]), "=r"(r[2]), "=r"(r[3]) : "r"(a));
}
__device__ __forceinline__ void mma16816(float* c, const uint32_t* a,
                                         uint32_t b0, uint32_t b1) {
    asm volatile(
        "mma.sync.aligned.m16n8k16.row.col.f32.f16.f16.f32 "
        "{%0,%1,%2,%3}, {%4,%5,%6,%7}, {%8,%9}, {%0,%1,%2,%3};"
        : "+f"(c[0]), "+f"(c[1]), "+f"(c[2]), "+f"(c[3])
        : "r"(a[0]), "r"(a[1]), "r"(a[2]), "r"(a[3]), "r"(b0), "r"(b1));
}
__device__ __forceinline__ void split32(float2 v, uint32_t& hi, uint32_t& lo) {
    v.x *= 32.f; v.y *= 32.f;
    __half2 h = __float22half2_rn(v);
    float2 b = __half22float2(h);
    __half2 L = __float22half2_rn(make_float2(v.x - b.x, v.y - b.y));
    hi = *(uint32_t*)&h;
    lo = *(uint32_t*)&L;
}

// ---------------------------------------------------------------------------
// Prep: split W into 2 f16 terms (scaled by 1024), zero aux accumulators
// ---------------------------------------------------------------------------
__global__ __launch_bounds__(256) void prep_kernel(const float* __restrict__ W) {
    int idx = blockIdx.x * 256 + threadIdx.x;
    if (blockIdx.x == 0) {
        ((float*)g_ssum)[threadIdx.x] = 0.f;
        ((float*)g_cnt )[threadIdx.x] = 0.f;
    }
    #pragma unroll
    for (int r = 0; r < 4; r++) {
        int i = idx + r * 16384;
        float4 v = ((const float4*)W)[i];
        float a0 = v.x * 1024.f, a1 = v.y * 1024.f, a2 = v.z * 1024.f, a3 = v.w * 1024.f;
        __half2 h01 = __float22half2_rn(make_float2(a0, a1));
        __half2 h23 = __float22half2_rn(make_float2(a2, a3));
        float2 b01 = __half22float2(h01);
        float2 b23 = __half22float2(h23);
        __half2 l01 = __float22half2_rn(make_float2(a0 - b01.x, a1 - b01.y));
        __half2 l23 = __float22half2_rn(make_float2(a2 - b23.x, a3 - b23.y));
        uint2 hw, lw;
        hw.x = *(uint32_t*)&h01; hw.y = *(uint32_t*)&h23;
        lw.x = *(uint32_t*)&l01; lw.y = *(uint32_t*)&l23;
        ((uint2*)g_W1)[i] = hw;
        ((uint2*)g_W2)[i] = lw;
    }
}

// ---------------------------------------------------------------------------
// Fused GEMM (split-f16 mma.sync, producer-converted A) + gating epilogue
// ---------------------------------------------------------------------------
__global__ __launch_bounds__(NT, 1) void moe_kernel(const float* __restrict__ X,
                                                    float* __restrict__ out) {
    extern __shared__ char dsm[];
    __shared__ float s_red[4][64];
    __shared__ float s_cnt[64];

    const int tid  = threadIdx.x;
    const int w    = tid >> 5;
    const int l    = tid & 31;
    const int tile = blockIdx.x;
    const float* Xt = X + (size_t)tile * BM * H_DIM;

    if (tid < 64) s_cnt[tid] = 0.f;

    // producer mapping: thread -> (token row pr, k-half ph)
    const int pr = tid >> 1;
    const int ph = tid & 1;
    const float4* Xrow = (const float4*)(Xt + (size_t)pr * H_DIM) + ph * 8;

    float4 xv[8];
    auto ldg_x = [&](int s) {
        const float4* p = Xrow + s * 16;    // BK=64 floats = 16 float4 per stage
        #pragma unroll
        for (int j = 0; j < 8; j++) xv[j] = p[j];
    };
    auto cvt_sts = [&](int s) {
        char* buf = dsm + (s % NBUF) * STAGE;
        #pragma unroll
        for (int j = 0; j < 4; j++) {       // 8 floats -> one 16B unit per plane
            float4 a = xv[2 * j], b = xv[2 * j + 1];
            uint32_t h0, l0, h1, l1, h2, l2, h3, l3;
            split32(make_float2(a.x, a.y), h0, l0);
            split32(make_float2(a.z, a.w), h1, l1);
            split32(make_float2(b.x, b.y), h2, l2);
            split32(make_float2(b.z, b.w), h3, l3);
            int u = (ph * 4 + j) ^ (pr & 7);
            *(uint4*)(buf + pr * 128 + u * 16)          = make_uint4(h0, h1, h2, h3);
            *(uint4*)(buf + ABYTES + pr * 128 + u * 16) = make_uint4(l0, l1, l2, l3);
        }
    };
    auto cp_w = [&](int s) {
        uint32_t wb = smem_u32(dsm) + (s % NBUF) * STAGE + 2 * ABYTES;
        const int k0 = s * BK;
        #pragma unroll
        for (int i = 0; i < 4; i++) {
            int ch = tid + i * NT;
            int e = ch >> 4, u = ch & 15;
            int split = u >> 3, kk = u & 7;
            int up = (u & 8) | ((u ^ (e & 7)) & 7);
            const __half* src = (split ? g_W2 : g_W1) + e * H_DIM + k0 + kk * 8;
            cp16(wb + e * 256 + up * 16, src);
        }
        asm volatile("cp.async.commit_group;");
    };

    float acc[2][4][4];
    #pragma unroll
    for (int i = 0; i < 2; i++)
        #pragma unroll
        for (int j = 0; j < 4; j++)
            #pragma unroll
            for (int q = 0; q < 4; q++) acc[i][j][q] = 0.f;

    // consumer mapping: warp -> (token group tg, expert half eh)
    const int tg = w >> 1, eh = w & 1;
    const int t8 = l >> 3, koff = t8 & 1;
    const int e_ld = eh * 32 + (t8 >> 1) * 8 + (l & 7);  // + pe*16
    const int a_row0 = tg * 32 + (l & 15);               // + mt*16
    const int a_k = l >> 4;

    // prologue
    ldg_x(0); cp_w(0);
    cvt_sts(0);
    ldg_x(1); cp_w(1);

    for (int s = 0; s < NSTAGE; s++) {
        if (s + 1 < NSTAGE) asm volatile("cp.async.wait_group 1;");
        else                asm volatile("cp.async.wait_group 0;");
        __syncthreads();

        if (s + 1 < NSTAGE) cvt_sts(s + 1);
        if (s + 2 < NSTAGE) { ldg_x(s + 2); cp_w(s + 2); }

        const char* buf = dsm + (s % NBUF) * STAGE;
        const uint32_t Ah = smem_u32(buf);
        const uint32_t Al = Ah + ABYTES;
        const uint32_t Wb = Ah + 2 * ABYTES;

        #pragma unroll
        for (int c16 = 0; c16 < 4; c16++) {
            const int ua = c16 * 2 + a_k;
            uint32_t ah[2][4], al[2][4];
            #pragma unroll
            for (int mt = 0; mt < 2; mt++) {
                int row = a_row0 + mt * 16;
                uint32_t off = row * 128 + ((ua ^ (row & 7)) + (ua & 8 ? 0 : 0)) * 16;
                // ua in 0..7, swizzle stays in 0..7
                off = row * 128 + ((ua ^ (row & 7)) & 7) * 16;
                ldsm4(ah[mt], Ah + off);
                ldsm4(al[mt], Al + off);
            }
            #pragma unroll
            for (int pe = 0; pe < 2; pe++) {
                const int e = e_ld + pe * 16;
                const int uph = ((c16 * 2 + koff) ^ (e & 7)) & 7;
                const uint32_t base = Wb + e * 256 + uph * 16;
                uint32_t bh[4], bl[4];
                ldsm4(bh, base);
                ldsm4(bl, base + 128);
                #pragma unroll
                for (int mt = 0; mt < 2; mt++) {
                    mma16816(acc[mt][2 * pe],     ah[mt], bh[0], bh[1]);
                    mma16816(acc[mt][2 * pe],     ah[mt], bl[0], bl[1]);
                    mma16816(acc[mt][2 * pe],     al[mt], bh[0], bh[1]);
                    mma16816(acc[mt][2 * pe + 1], ah[mt], bh[2], bh[3]);
                    mma16816(acc[mt][2 * pe + 1], ah[mt], bl[2], bl[3]);
                    mma16816(acc[mt][2 * pe + 1], al[mt], bh[2], bh[3]);
                }
            }
        }
    }
    __syncthreads();   // protect dsm before reuse as score buffer

    // ---------------- epilogue: scores to smem ----------------
    float* S = (float*)dsm;               // [128][65]
    {
        constexpr float INV = 1.0f / 32768.0f;
        const int r0 = tg * 32 + (l >> 2);
        const int c0 = eh * 32 + (l & 3) * 2;
        #pragma unroll
        for (int mt = 0; mt < 2; mt++)
            #pragma unroll
            for (int nb = 0; nb < 4; nb++) {
                int rr = r0 + mt * 16;
                int cc = c0 + nb * 8;
                S[rr * 65 + cc]           = acc[mt][nb][0] * INV;
                S[rr * 65 + cc + 1]       = acc[mt][nb][1] * INV;
                S[(rr + 8) * 65 + cc]     = acc[mt][nb][2] * INV;
                S[(rr + 8) * 65 + cc + 1] = acc[mt][nb][3] * INV;
            }
    }
    __syncthreads();

    if (tid < 128) {
        float sc[64];
        #pragma unroll
        for (int e = 0; e < 64; e++) sc[e] = S[tid * 65 + e];

        // softmax
        float m = sc[0];
        #pragma unroll
        for (int e = 1; e < 64; e++) m = fmaxf(m, sc[e]);
        float ssum = 0.f;
        #pragma unroll
        for (int e = 0; e < 64; e++) { sc[e] = expf(sc[e] - m); ssum += sc[e]; }
        float inv = 1.0f / ssum;
        #pragma unroll
        for (int e = 0; e < 64; e++) sc[e] *= inv;

        // group maxima
        float gm[8];
        #pragma unroll
        for (int g = 0; g < 8; g++) {
            float a = sc[g * 8];
            #pragma unroll
            for (int j = 1; j < 8; j++) a = fmaxf(a, sc[g * 8 + j]);
            gm[g] = a;
        }
        // top-3 groups
        unsigned keep = 0;
        #pragma unroll
        for (int r = 0; r < 3; r++) {
            float bv = -1.f; int bi = 0;
            #pragma unroll
            for (int g = 0; g < 8; g++) {
                bool ok = !((keep >> g) & 1) && (gm[g] > bv);
                if (ok) { bv = gm[g]; bi = g; }
            }
            keep |= 1u << bi;
        }
        // top-6 experts in kept groups
        ull picked = 0;
        float wsum = 0.f;
        int idxs[6]; float vals[6];
        #pragma unroll
        for (int r = 0; r < 6; r++) {
            float bv = -1.f; int bi = 0;
            #pragma unroll
            for (int e = 0; e < 64; e++) {
                bool ok = ((keep >> (e >> 3)) & 1) && !((picked >> e) & 1) && (sc[e] > bv);
                if (ok) { bv = sc[e]; bi = e; }
            }
            picked |= 1ull << bi;
            idxs[r] = bi; vals[r] = bv; wsum += bv;
        }
        float inv2 = 1.0f / (wsum + 1e-20f);

        const int t = tile * BM + tid;
        #pragma unroll
        for (int r = 0; r < 6; r++) {
            out[t * TOPK + r]                = (float)idxs[r];
            out[T_TOK * TOPK + t * TOPK + r] = vals[r] * inv2;
        }

        // aux accumulators
        #pragma unroll
        for (int e = 0; e < 64; e++) {
            float v = sc[e];
            v += __shfl_xor_sync(0xffffffffu, v, 16);
            v += __shfl_xor_sync(0xffffffffu, v, 8);
            v += __shfl_xor_sync(0xffffffffu, v, 4);
            v += __shfl_xor_sync(0xffffffffu, v, 2);
            v += __shfl_xor_sync(0xffffffffu, v, 1);
            if (l == 0) s_red[w][e] = v;
        }
        #pragma unroll
        for (int r = 0; r < 6; r++) atomicAdd(&s_cnt[idxs[r]], 1.0f);
    }
    __syncthreads();
    if (tid < 64) {
        float a = s_red[0][tid] + s_red[1][tid] + s_red[2][tid] + s_red[3][tid];
        int b = (tile * BM) / S_SEQ;
        atomicAdd(&g_ssum[b][tid], a);
        atomicAdd(&g_cnt [b][tid], s_cnt[tid]);
    }
}

// aux_loss = ALPHA * mean_b sum_e (cnt/(S*K/E)) * (ssum/S)
__global__ void aux_kernel(float* __restrict__ out) {
    __shared__ float red[256];
    int tid = threadIdx.x;
    red[tid] = ((const float*)g_cnt)[tid] * ((const float*)g_ssum)[tid];
    __syncthreads();
    for (int s2 = 128; s2 > 0; s2 >>= 1) {
        if (tid < s2) red[tid] += red[tid + s2];
        __syncthreads();
    }
    if (tid == 0)
        out[2 * T_TOK * TOPK] = red[0] * (0.001f / (4.0f * 384.0f * 4096.0f));
}

extern "C" void kernel_launch(void* const* d_in, const int* in_sizes, int n_in,
                              void* d_out, int out_size) {
    const float* X = (const float*)d_in[0];   // [4,4096,4096] fp32
    const float* W = (const float*)d_in[1];   // [64,4096] fp32
    float* out = (float*)d_out;

    cudaFuncSetAttribute(moe_kernel, cudaFuncAttributeMaxDynamicSharedMemorySize, DYN);
    prep_kernel<<<64, 256>>>(W);
    moe_kernel<<<T_TOK / BM, NT, DYN>>>(X, out);
    aux_kernel<<<1, 256>>>(out);
}